// round 3
// baseline (speedup 1.0000x reference)
#include <cuda_runtime.h>

// Warper3d: 3D trilinear warp (grid_sample semantics, align_corners=False,
// padding_mode='border') with the reference's exact coordinate composition.
//
// Shapes (fixed for this problem):
//   img : [B=4, C=1, D=64, H=192, W=192] float32
//   flow: [B=4, 3,    D=64, H=192, W=192] float32
//   out : [B=4, 1,    D=64, H=192, W=192] float32

#define BB 4
#define DD 64
#define HH 192
#define WW 192
#define SP (DD * HH * WW)          // 2,359,296 spatial elements per batch
#define TOTAL (BB * SP)            // 9,437,184 output elements
#define NTHREADS 256
#define NBLOCKS ((TOTAL / 4 + NTHREADS - 1) / NTHREADS)   // 9216

__global__ __launch_bounds__(NTHREADS)
void warp3d_kernel(const float* __restrict__ img,
                   const float* __restrict__ flow,
                   float* __restrict__ out)
{
    int t = blockIdx.x * NTHREADS + threadIdx.x;
    int i4 = t << 2;                       // 4 consecutive W-voxels per thread
    if (i4 >= TOTAL) return;

    int b = i4 / SP;
    int s = i4 - b * SP;                   // spatial index, multiple of 4
    int x = s % WW;
    int zy = s / WW;
    int y = zy % HH;
    int z = zy / HH;

    const float* fb = flow + (size_t)b * 3 * SP;
    float4 fx = *(const float4*)(fb + s);
    float4 fy = *(const float4*)(fb + SP + s);
    float4 fz = *(const float4*)(fb + 2 * SP + s);

    const float* ib = img + (size_t)b * SP;

    float4 res;
    float* resp = (float*)&res;
    const float* fxp = (const float*)&fx;
    const float* fyp = (const float*)&fy;
    const float* fzp = (const float*)&fz;

    #pragma unroll
    for (int k = 0; k < 4; k++) {
        float vx = (float)(x + k) + fxp[k];
        float vy = (float)y + fyp[k];
        float vz = (float)z + fzp[k];

        // Exact replication of the reference composition:
        //   g = 2*v/(S-1) - 1 ;  i = ((g+1)*S - 1)*0.5 ;  clip to [0, S-1]
        float gx = 2.0f * vx / (float)(WW - 1) - 1.0f;
        float gy = 2.0f * vy / (float)(HH - 1) - 1.0f;
        float gz = 2.0f * vz / (float)(DD - 1) - 1.0f;
        float ix = ((gx + 1.0f) * (float)WW - 1.0f) * 0.5f;
        float iy = ((gy + 1.0f) * (float)HH - 1.0f) * 0.5f;
        float iz = ((gz + 1.0f) * (float)DD - 1.0f) * 0.5f;
        ix = fminf(fmaxf(ix, 0.0f), (float)(WW - 1));
        iy = fminf(fmaxf(iy, 0.0f), (float)(HH - 1));
        iz = fminf(fmaxf(iz, 0.0f), (float)(DD - 1));

        float x0f = floorf(ix); float wx = ix - x0f;
        float y0f = floorf(iy); float wy = iy - y0f;
        float z0f = floorf(iz); float wz = iz - z0f;

        int x0 = (int)x0f; int x1 = min(x0 + 1, WW - 1);
        int y0 = (int)y0f; int y1 = min(y0 + 1, HH - 1);
        int z0 = (int)z0f; int z1 = min(z0 + 1, DD - 1);

        const float* p00 = ib + (z0 * HH + y0) * WW;
        const float* p01 = ib + (z0 * HH + y1) * WW;
        const float* p10 = ib + (z1 * HH + y0) * WW;
        const float* p11 = ib + (z1 * HH + y1) * WW;

        float v000 = __ldg(p00 + x0);
        float v001 = __ldg(p00 + x1);
        float v010 = __ldg(p01 + x0);
        float v011 = __ldg(p01 + x1);
        float v100 = __ldg(p10 + x0);
        float v101 = __ldg(p10 + x1);
        float v110 = __ldg(p11 + x0);
        float v111 = __ldg(p11 + x1);

        // lerp chain: x, then y, then z (continuous => matches ref numerics)
        float c00 = fmaf(wx, v001 - v000, v000);
        float c01 = fmaf(wx, v011 - v010, v010);
        float c10 = fmaf(wx, v101 - v100, v100);
        float c11 = fmaf(wx, v111 - v110, v110);
        float c0  = fmaf(wy, c01 - c00, c00);
        float c1  = fmaf(wy, c11 - c10, c10);
        resp[k]   = fmaf(wz, c1 - c0, c0);
    }

    *(float4*)(out + i4) = res;
}

extern "C" void kernel_launch(void* const* d_in, const int* in_sizes, int n_in,
                              void* d_out, int out_size)
{
    const float* img  = (const float*)d_in[0];
    const float* flow = (const float*)d_in[1];
    float* out = (float*)d_out;

    warp3d_kernel<<<NBLOCKS, NTHREADS>>>(img, flow, out);
}

// round 4
// speedup vs baseline: 1.0647x; 1.0647x over previous
#include <cuda_runtime.h>

// Warper3d: 3D trilinear warp (grid_sample, align_corners=False, border pad).
//   img : [B=4, 1, D=64, H=192, W=192] f32
//   flow: [B=4, 3, D=64, H=192, W=192] f32
//   out : [B=4, 1, D=64, H=192, W=192] f32
//
// R3 ncu: L1tex-bound (73%) on scalar gathers; DRAM only 27%.
// This version: 1 voxel/thread with x-contiguous lanes (fewer L1 lines per
// gather wavefront), 64x2x2 block tiles (cross-warp L1 reuse in y/z), and
// one-FMA coordinate transform ix = vx*S/(S-1) - 0.5 (exact algebraic
// simplification of the reference composition).

#define BB 4
#define DD 64
#define HH 192
#define WW 192
#define SP (DD * HH * WW)

#define TX 64
#define TY 2
#define TZ 2

__global__ __launch_bounds__(TX * TY * TZ)
void warp3d_kernel(const float* __restrict__ img,
                   const float* __restrict__ flow,
                   float* __restrict__ out)
{
    int x = blockIdx.x * TX + threadIdx.x;
    int y = blockIdx.y * TY + threadIdx.y;
    int zb = blockIdx.z;                    // [0,128): z-tile (32) x batch (4)
    int z = (zb & 31) * TZ + threadIdx.z;
    int b = zb >> 5;

    int s = (z * HH + y) * WW + x;

    const float* fb = flow + (size_t)b * 3 * SP;
    float fx = __ldg(fb + s);
    float fy = __ldg(fb + SP + s);
    float fz = __ldg(fb + 2 * SP + s);

    // Reference composition gx=2v/(S-1)-1; ix=((gx+1)*S-1)/2  ==  v*S/(S-1) - 0.5
    const float KX = (float)WW / (float)(WW - 1);
    const float KY = (float)HH / (float)(HH - 1);
    const float KZ = (float)DD / (float)(DD - 1);

    float ix = fmaf((float)x + fx, KX, -0.5f);
    float iy = fmaf((float)y + fy, KY, -0.5f);
    float iz = fmaf((float)z + fz, KZ, -0.5f);
    ix = fminf(fmaxf(ix, 0.0f), (float)(WW - 1));
    iy = fminf(fmaxf(iy, 0.0f), (float)(HH - 1));
    iz = fminf(fmaxf(iz, 0.0f), (float)(DD - 1));

    float x0f = floorf(ix); float wx = ix - x0f;
    float y0f = floorf(iy); float wy = iy - y0f;
    float z0f = floorf(iz); float wz = iz - z0f;

    int x0 = (int)x0f; int x1 = min(x0 + 1, WW - 1);
    int y0 = (int)y0f; int y1 = min(y0 + 1, HH - 1);
    int z0 = (int)z0f; int z1 = min(z0 + 1, DD - 1);

    const float* ib = img + (size_t)b * SP;
    const float* p00 = ib + (z0 * HH + y0) * WW;
    const float* p01 = ib + (z0 * HH + y1) * WW;
    const float* p10 = ib + (z1 * HH + y0) * WW;
    const float* p11 = ib + (z1 * HH + y1) * WW;

    float v000 = __ldg(p00 + x0);
    float v001 = __ldg(p00 + x1);
    float v010 = __ldg(p01 + x0);
    float v011 = __ldg(p01 + x1);
    float v100 = __ldg(p10 + x0);
    float v101 = __ldg(p10 + x1);
    float v110 = __ldg(p11 + x0);
    float v111 = __ldg(p11 + x1);

    float c00 = fmaf(wx, v001 - v000, v000);
    float c01 = fmaf(wx, v011 - v010, v010);
    float c10 = fmaf(wx, v101 - v100, v100);
    float c11 = fmaf(wx, v111 - v110, v110);
    float c0  = fmaf(wy, c01 - c00, c00);
    float c1  = fmaf(wy, c11 - c10, c10);
    float r   = fmaf(wz, c1 - c0, c0);

    out[(size_t)b * SP + s] = r;
}

extern "C" void kernel_launch(void* const* d_in, const int* in_sizes, int n_in,
                              void* d_out, int out_size)
{
    const float* img  = (const float*)d_in[0];
    const float* flow = (const float*)d_in[1];
    float* out = (float*)d_out;

    dim3 block(TX, TY, TZ);                       // 256 threads
    dim3 grid(WW / TX, HH / TY, (DD / TZ) * BB);  // 3 x 96 x 128
    warp3d_kernel<<<grid, block>>>(img, flow, out);
}